// round 5
// baseline (speedup 1.0000x reference)
#include <cuda_runtime.h>
#include <math.h>

// ROC-Star pairwise loss, B=256, E=8192, C=19 (shapes derived at runtime).
// Three kernels:
//   prep_kernel : [0,chunks) blocks: coalesced per-chunk epoch-positive
//                 counts -> integer atomicAdd into d_cap[c].
//                 [chunks, chunks+Cn) blocks: FLAT batch setup — one thread
//                 per (c, i), 2 independent loads, no serial loop.
//   loss_kernel : per (chunk, class) block: ballot-compact selected epoch
//                 elements, pairwise relu^2 vs batch (thread==batch index,
//                 masked via 1e30), shuffle reduce, write partial.
//   finalize    : 1 block: per-class sums + degenerate handling + mean;
//                 zeroes d_cap for the next graph replay.

#define TPB   256
#define MAXC  32
#define MAXCH 64

__device__ float d_Apos[MAXC * TPB];   // y_i if batch-pos else 1e30
__device__ float d_Aneg[MAXC * TPB];   // -y_i if batch-neg else 1e30
__device__ int   d_cap[MAXC];          // zero-init; finalize re-zeroes
__device__ float d_part[MAXC * MAXCH];

__global__ void prep_kernel(const float* __restrict__ epoch_true,
                            const float* __restrict__ y_pred,
                            const float* __restrict__ y_true,
                            int Bn, int Cn, int En, int chunks)
{
    if ((int)blockIdx.x < chunks) {
        // ---- count epoch positives for this 256-row chunk, coalesced ----
        int w = threadIdx.x >> 5, l = threadIdx.x & 31;
        const int rows_per_warp = TPB / 8;            // 32 rows per warp
        int row0 = blockIdx.x * TPB + w * rows_per_warp;
        int cnt = 0;
        if (l < Cn) {
            const float* base = epoch_true + (size_t)row0 * Cn + l;
            #pragma unroll 16
            for (int r = 0; r < rows_per_warp; r++) {
                if (row0 + r < En)
                    cnt += (base[(size_t)r * Cn] >= 0.5f) ? 1 : 0;
            }
        }
        __shared__ int scnt[8][MAXC];
        if (l < MAXC) scnt[w][l] = cnt;
        __syncthreads();
        if ((int)threadIdx.x < Cn) {
            int t = 0;
            #pragma unroll
            for (int k = 0; k < 8; k++) t += scnt[k][threadIdx.x];
            atomicAdd(&d_cap[threadIdx.x], t);   // integer: deterministic
        }
    } else {
        // ---- flat batch setup: block handles class c, thread handles i ----
        int c = (int)blockIdx.x - chunks;        // 0..Cn-1
        int i = threadIdx.x;                     // 0..TPB-1
        float ap = 1e30f, an = 1e30f;
        if (i < Bn) {
            float y   = y_pred[i * Cn + c];
            bool  pos = y_true[i * Cn + c] >= 0.5f;
            if (pos) ap =  y;
            else     an = -y;
        }
        d_Apos[c * TPB + i] = ap;
        d_Aneg[c * TPB + i] = an;
    }
}

__global__ void loss_kernel(const float* __restrict__ epoch_pred,
                            const float* __restrict__ epoch_true,
                            const float* __restrict__ rand_pos,
                            const float* __restrict__ rand_neg,
                            const float* __restrict__ gamma,
                            int Cn, int En)
{
    int c    = blockIdx.y;
    int tid  = threadIdx.x;
    int lane = tid & 31, w = tid >> 5;
    int j    = blockIdx.x * TPB + tid;

    float g = gamma[c];
    float p = 1000.0f / fmaxf((float)d_cap[c], 1.0f);

    bool selpos = false, selneg = false;
    float tval = 0.f;
    if (j < En) {
        int off = j * Cn + c;
        float e   = epoch_pred[off];
        bool  etb = epoch_true[off] >= 0.5f;
        float rp  = rand_pos[off];
        float rn  = rand_neg[off];
        if (etb) { selpos = rp < p; tval = g - e; }   // vs batch negs
        else     { selneg = rn < p; tval = e + g; }   // vs batch pos
    }

    // ---- deterministic ballot compaction ----
    __shared__ float s_tn[TPB], s_tp[TPB];
    __shared__ int wcN[8], wcP[8];
    unsigned bn = __ballot_sync(0xffffffffu, selneg);
    unsigned bp = __ballot_sync(0xffffffffu, selpos);
    if (lane == 0) { wcN[w] = __popc(bn); wcP[w] = __popc(bp); }
    __syncthreads();
    int offN = 0, offP = 0, totN = 0, totP = 0;
    #pragma unroll
    for (int k = 0; k < 8; k++) {
        int vn = wcN[k], vp = wcP[k];
        if (k < w) { offN += vn; offP += vp; }
        totN += vn; totP += vp;
    }
    unsigned lmask = (1u << lane) - 1u;
    if (selneg) s_tn[offN + __popc(bn & lmask)] = tval;
    if (selpos) s_tp[offP + __popc(bp & lmask)] = tval;
    __syncthreads();

    // ---- pairwise: thread owns batch element tid ----
    float apos = d_Apos[c * TPB + tid];
    float aneg = d_Aneg[c * TPB + tid];
    float acc = 0.f;
    #pragma unroll 4
    for (int k = 0; k < totN; k++) {
        float d = s_tn[k] - apos;        // e + g - y
        float r = fmaxf(d, 0.f);
        acc = fmaf(r, r, acc);
    }
    #pragma unroll 4
    for (int k = 0; k < totP; k++) {
        float d = s_tp[k] - aneg;        // y - e + g
        float r = fmaxf(d, 0.f);
        acc = fmaf(r, r, acc);
    }

    // ---- reduce: warp shuffle, then warp 0 over 8 partials ----
    #pragma unroll
    for (int o = 16; o > 0; o >>= 1)
        acc += __shfl_down_sync(0xffffffffu, acc, o);
    __shared__ float wsum[8];
    if (lane == 0) wsum[w] = acc;
    __syncthreads();
    if (w == 0) {
        float v = (lane < 8) ? wsum[lane] : 0.f;
        #pragma unroll
        for (int o = 4; o > 0; o >>= 1)
            v += __shfl_down_sync(0xffffffffu, v, o);
        if (lane == 0) d_part[c * MAXCH + blockIdx.x] = v;
    }
}

__global__ void finalize_kernel(const float* __restrict__ y_pred,
                                const float* __restrict__ y_true,
                                float* __restrict__ out,
                                int Bn, int Cn, int chunks)
{
    int tid  = threadIdx.x;
    int lane = tid & 31, w = tid >> 5;

    // warp w handles classes w, w+8, ... (deterministic shuffle reductions)
    __shared__ float sres[MAXC];
    for (int cc = w; cc < Cn; cc += 8) {
        float m = 0.f;
        for (int k = lane; k < chunks; k += 32)
            m += d_part[cc * MAXCH + k];
        float sy = 0.f;
        int   np = 0;
        for (int i = lane; i < Bn; i += 32) {
            float y = y_pred[i * Cn + cc];
            sy += y;
            np += (y_true[i * Cn + cc] >= 0.5f) ? 1 : 0;
        }
        #pragma unroll
        for (int o = 16; o > 0; o >>= 1) {
            m  += __shfl_down_sync(0xffffffffu, m,  o);
            sy += __shfl_down_sync(0xffffffffu, sy, o);
            np += __shfl_down_sync(0xffffffffu, np, o);
        }
        if (lane == 0) {
            float res = m / 1000.0f;            // m2/MAX_POS + m3/MAX_NEG
            if (isnan(res)) res = 0.f;
            if (np == 0 || np == Bn) res = sy * 1e-8f;
            sres[cc] = res;
        }
    }
    // reset subsample caps for the next graph replay
    if (tid < MAXC) d_cap[tid] = 0;
    __syncthreads();
    if (w == 0) {
        float r = (lane < Cn) ? sres[lane] : 0.f;
        #pragma unroll
        for (int o = 16; o > 0; o >>= 1)
            r += __shfl_down_sync(0xffffffffu, r, o);
        if (lane == 0) out[0] = r / (float)Cn;
    }
}

extern "C" void kernel_launch(void* const* d_in, const int* in_sizes, int n_in,
                              void* d_out, int out_size)
{
    const float* y_pred     = (const float*)d_in[0];
    const float* y_true     = (const float*)d_in[1];
    const float* epoch_pred = (const float*)d_in[2];
    const float* epoch_true = (const float*)d_in[3];
    const float* gamma      = (const float*)d_in[4];
    const float* rand_pos   = (const float*)d_in[5];
    const float* rand_neg   = (const float*)d_in[6];

    int Cn = in_sizes[4];            // gamma: [C]
    int Bn = in_sizes[0] / Cn;       // y_pred: [B, C]
    int En = in_sizes[2] / Cn;       // epoch_pred: [E, C]
    int chunks = (En + TPB - 1) / TPB;

    prep_kernel<<<chunks + Cn, TPB>>>(epoch_true, y_pred, y_true,
                                      Bn, Cn, En, chunks);
    dim3 grid(chunks, Cn);
    loss_kernel<<<grid, TPB>>>(epoch_pred, epoch_true, rand_pos, rand_neg,
                               gamma, Cn, En);
    finalize_kernel<<<1, TPB>>>(y_pred, y_true, (float*)d_out, Bn, Cn, chunks);
}

// round 6
// speedup vs baseline: 1.4602x; 1.4602x over previous
#include <cuda_runtime.h>
#include <math.h>

// ROC-Star pairwise loss, B=256, E=8192, C=19 (shapes derived at runtime).
// TWO kernels (prep eliminated — each loss block is self-sufficient):
//   loss_kernel : per (chunk, class) block:
//                   1. redundantly count epoch positives of its class
//                      (32 indep loads/thread, fixed-order block reduce)
//                   2. load own batch y values -> apos/aneg registers
//                   3. ballot-compact selected epoch elems, pairwise relu^2,
//                      shuffle reduce, write partial.
//   finalize    : 1 block: per-class sums + degenerate handling + mean.

#define TPB   256
#define MAXC  32
#define MAXCH 64

__device__ float d_part[MAXC * MAXCH];

__global__ void __launch_bounds__(TPB)
loss_kernel(const float* __restrict__ epoch_pred,
            const float* __restrict__ epoch_true,
            const float* __restrict__ rand_pos,
            const float* __restrict__ rand_neg,
            const float* __restrict__ gamma,
            const float* __restrict__ y_pred,
            const float* __restrict__ y_true,
            int Bn, int Cn, int En)
{
    int c    = blockIdx.y;
    int tid  = threadIdx.x;
    int lane = tid & 31, w = tid >> 5;
    int j    = blockIdx.x * TPB + tid;

    // ---- issue all global loads up front (max MLP) ----
    float g = gamma[c];

    // this thread's epoch element (for selection)
    float e = 0.f, rp = 2.f, rn = 2.f;
    bool  etb = false;
    if (j < En) {
        int off = j * Cn + c;
        e   = epoch_pred[off];
        etb = epoch_true[off] >= 0.5f;
        rp  = rand_pos[off];
        rn  = rand_neg[off];
    }

    // this thread's batch element (for pairwise)
    float apos = 1e30f, aneg = 1e30f;
    if (tid < Bn) {
        float y   = y_pred[tid * Cn + c];
        bool  pos = y_true[tid * Cn + c] >= 0.5f;
        if (pos) apos =  y;
        else     aneg = -y;
    }

    // redundant per-block count of epoch positives for class c
    int cnt = 0;
    {
        const float* base = epoch_true + c;
        int nrows = (En + TPB - 1) / TPB;
        #pragma unroll 8
        for (int r = 0; r < nrows; r++) {
            int row = r * TPB + tid;
            if (row < En)
                cnt += (base[(size_t)row * Cn] >= 0.5f) ? 1 : 0;
        }
    }
    // fixed-order integer reduction -> cap (deterministic)
    #pragma unroll
    for (int o = 16; o > 0; o >>= 1)
        cnt += __shfl_down_sync(0xffffffffu, cnt, o);
    __shared__ int s_wcnt[8];
    if (lane == 0) s_wcnt[w] = cnt;
    __syncthreads();
    int cap = 0;
    #pragma unroll
    for (int k = 0; k < 8; k++) cap += s_wcnt[k];

    float p = 1000.0f / fmaxf((float)cap, 1.0f);

    bool selpos = false, selneg = false;
    float tval;
    if (etb) { selpos = rp < p; tval = g - e; }   // vs batch negs
    else     { selneg = rn < p; tval = e + g; }   // vs batch pos

    // ---- deterministic ballot compaction ----
    __shared__ float s_tn[TPB], s_tp[TPB];
    __shared__ int wcN[8], wcP[8];
    unsigned bn = __ballot_sync(0xffffffffu, selneg);
    unsigned bp = __ballot_sync(0xffffffffu, selpos);
    if (lane == 0) { wcN[w] = __popc(bn); wcP[w] = __popc(bp); }
    __syncthreads();
    int offN = 0, offP = 0, totN = 0, totP = 0;
    #pragma unroll
    for (int k = 0; k < 8; k++) {
        int vn = wcN[k], vp = wcP[k];
        if (k < w) { offN += vn; offP += vp; }
        totN += vn; totP += vp;
    }
    unsigned lmask = (1u << lane) - 1u;
    if (selneg) s_tn[offN + __popc(bn & lmask)] = tval;
    if (selpos) s_tp[offP + __popc(bp & lmask)] = tval;
    __syncthreads();

    // ---- pairwise: thread owns batch element tid ----
    float acc = 0.f;
    #pragma unroll 4
    for (int k = 0; k < totN; k++) {
        float d = s_tn[k] - apos;        // e + g - y
        float r = fmaxf(d, 0.f);
        acc = fmaf(r, r, acc);
    }
    #pragma unroll 4
    for (int k = 0; k < totP; k++) {
        float d = s_tp[k] - aneg;        // y - e + g
        float r = fmaxf(d, 0.f);
        acc = fmaf(r, r, acc);
    }

    // ---- reduce: warp shuffle, then warp 0 over 8 partials ----
    #pragma unroll
    for (int o = 16; o > 0; o >>= 1)
        acc += __shfl_down_sync(0xffffffffu, acc, o);
    __shared__ float wsum[8];
    if (lane == 0) wsum[w] = acc;
    __syncthreads();
    if (w == 0) {
        float v = (lane < 8) ? wsum[lane] : 0.f;
        #pragma unroll
        for (int o = 4; o > 0; o >>= 1)
            v += __shfl_down_sync(0xffffffffu, v, o);
        if (lane == 0) d_part[c * MAXCH + blockIdx.x] = v;
    }
}

__global__ void finalize_kernel(const float* __restrict__ y_pred,
                                const float* __restrict__ y_true,
                                float* __restrict__ out,
                                int Bn, int Cn, int chunks)
{
    int tid  = threadIdx.x;
    int lane = tid & 31, w = tid >> 5;

    // warp w handles classes w, w+8, ... (deterministic shuffle reductions)
    __shared__ float sres[MAXC];
    for (int cc = w; cc < Cn; cc += 8) {
        float m = 0.f;
        for (int k = lane; k < chunks; k += 32)
            m += d_part[cc * MAXCH + k];
        float sy = 0.f;
        int   np = 0;
        for (int i = lane; i < Bn; i += 32) {
            float y = y_pred[i * Cn + cc];
            sy += y;
            np += (y_true[i * Cn + cc] >= 0.5f) ? 1 : 0;
        }
        #pragma unroll
        for (int o = 16; o > 0; o >>= 1) {
            m  += __shfl_down_sync(0xffffffffu, m,  o);
            sy += __shfl_down_sync(0xffffffffu, sy, o);
            np += __shfl_down_sync(0xffffffffu, np, o);
        }
        if (lane == 0) {
            float res = m / 1000.0f;            // m2/MAX_POS + m3/MAX_NEG
            if (isnan(res)) res = 0.f;
            if (np == 0 || np == Bn) res = sy * 1e-8f;
            sres[cc] = res;
        }
    }
    __syncthreads();
    if (w == 0) {
        float r = (lane < Cn) ? sres[lane] : 0.f;
        #pragma unroll
        for (int o = 16; o > 0; o >>= 1)
            r += __shfl_down_sync(0xffffffffu, r, o);
        if (lane == 0) out[0] = r / (float)Cn;
    }
}

extern "C" void kernel_launch(void* const* d_in, const int* in_sizes, int n_in,
                              void* d_out, int out_size)
{
    const float* y_pred     = (const float*)d_in[0];
    const float* y_true     = (const float*)d_in[1];
    const float* epoch_pred = (const float*)d_in[2];
    const float* epoch_true = (const float*)d_in[3];
    const float* gamma      = (const float*)d_in[4];
    const float* rand_pos   = (const float*)d_in[5];
    const float* rand_neg   = (const float*)d_in[6];

    int Cn = in_sizes[4];            // gamma: [C]
    int Bn = in_sizes[0] / Cn;       // y_pred: [B, C]
    int En = in_sizes[2] / Cn;       // epoch_pred: [E, C]
    int chunks = (En + TPB - 1) / TPB;

    dim3 grid(chunks, Cn);
    loss_kernel<<<grid, TPB>>>(epoch_pred, epoch_true, rand_pos, rand_neg,
                               gamma, y_pred, y_true, Bn, Cn, En);
    finalize_kernel<<<1, TPB>>>(y_pred, y_true, (float*)d_out, Bn, Cn, chunks);
}

// round 7
// speedup vs baseline: 2.0454x; 1.4008x over previous
#include <cuda_runtime.h>
#include <math.h>

// ROC-Star pairwise loss, B=256, E=8192, C=19 (shapes derived at runtime).
// Three minimal kernels:
//   count_kernel : one block per class. Counts epoch positives (cap),
//                  batch positives (npos) and sum(y_pred) for that class.
//                  Plain per-class stores — no atomics, replay-safe.
//   loss_kernel  : per (chunk, class) block: ballot-compact selected epoch
//                  elements (p = 1000/cap broadcast from d_cap), pairwise
//                  relu^2 vs batch (thread==batch index, masked via 1e30),
//                  shuffle reduce, write partial.
//   finalize     : 1 block: reduce d_part (L2-hot) + degenerate handling
//                  + mean over classes.

#define TPB   256
#define MAXC  32
#define MAXCH 64

__device__ int   d_cap[MAXC];
__device__ int   d_npos[MAXC];
__device__ float d_sumyp[MAXC];
__device__ float d_part[MAXC * MAXCH];

__global__ void __launch_bounds__(TPB)
count_kernel(const float* __restrict__ epoch_true,
             const float* __restrict__ y_pred,
             const float* __restrict__ y_true,
             int Bn, int Cn, int En)
{
    int c    = blockIdx.x;
    int tid  = threadIdx.x;
    int lane = tid & 31, w = tid >> 5;

    // epoch positives for class c: 32 independent strided loads per thread
    int cnt = 0;
    {
        const float* base = epoch_true + c;
        int nrows = (En + TPB - 1) / TPB;
        #pragma unroll 8
        for (int r = 0; r < nrows; r++) {
            int row = r * TPB + tid;
            if (row < En)
                cnt += (base[(size_t)row * Cn] >= 0.5f) ? 1 : 0;
        }
    }
    // batch stats for class c
    float sy = 0.f;
    int   np = 0;
    if (tid < Bn) {
        float y = y_pred[tid * Cn + c];
        sy = y;
        np = (y_true[tid * Cn + c] >= 0.5f) ? 1 : 0;
    }

    // fixed-order reductions (deterministic)
    #pragma unroll
    for (int o = 16; o > 0; o >>= 1) {
        cnt += __shfl_down_sync(0xffffffffu, cnt, o);
        np  += __shfl_down_sync(0xffffffffu, np,  o);
        sy  += __shfl_down_sync(0xffffffffu, sy,  o);
    }
    __shared__ int   s_c[8], s_n[8];
    __shared__ float s_s[8];
    if (lane == 0) { s_c[w] = cnt; s_n[w] = np; s_s[w] = sy; }
    __syncthreads();
    if (tid == 0) {
        int tc = 0, tn = 0; float ts = 0.f;
        #pragma unroll
        for (int k = 0; k < 8; k++) { tc += s_c[k]; tn += s_n[k]; ts += s_s[k]; }
        d_cap[c]   = tc;
        d_npos[c]  = tn;
        d_sumyp[c] = ts;
    }
}

__global__ void __launch_bounds__(TPB)
loss_kernel(const float* __restrict__ epoch_pred,
            const float* __restrict__ epoch_true,
            const float* __restrict__ rand_pos,
            const float* __restrict__ rand_neg,
            const float* __restrict__ gamma,
            const float* __restrict__ y_pred,
            const float* __restrict__ y_true,
            int Bn, int Cn, int En)
{
    int c    = blockIdx.y;
    int tid  = threadIdx.x;
    int lane = tid & 31, w = tid >> 5;
    int j    = blockIdx.x * TPB + tid;

    // ---- issue all global loads up front (max MLP) ----
    float g = gamma[c];
    float p = 1000.0f / fmaxf((float)d_cap[c], 1.0f);   // L2-hot broadcast

    float e = 0.f, rp = 2.f, rn = 2.f;
    bool  etb = false;
    if (j < En) {
        int off = j * Cn + c;
        e   = epoch_pred[off];
        etb = epoch_true[off] >= 0.5f;
        rp  = rand_pos[off];
        rn  = rand_neg[off];
    }

    float apos = 1e30f, aneg = 1e30f;
    if (tid < Bn) {
        float y   = y_pred[tid * Cn + c];
        bool  pos = y_true[tid * Cn + c] >= 0.5f;
        if (pos) apos =  y;
        else     aneg = -y;
    }

    bool selpos = false, selneg = false;
    float tval;
    if (etb) { selpos = rp < p; tval = g - e; }   // vs batch negs
    else     { selneg = rn < p; tval = e + g; }   // vs batch pos

    // ---- deterministic ballot compaction ----
    __shared__ float s_tn[TPB], s_tp[TPB];
    __shared__ int wcN[8], wcP[8];
    unsigned bn = __ballot_sync(0xffffffffu, selneg);
    unsigned bp = __ballot_sync(0xffffffffu, selpos);
    if (lane == 0) { wcN[w] = __popc(bn); wcP[w] = __popc(bp); }
    __syncthreads();
    int offN = 0, offP = 0, totN = 0, totP = 0;
    #pragma unroll
    for (int k = 0; k < 8; k++) {
        int vn = wcN[k], vp = wcP[k];
        if (k < w) { offN += vn; offP += vp; }
        totN += vn; totP += vp;
    }
    unsigned lmask = (1u << lane) - 1u;
    if (selneg) s_tn[offN + __popc(bn & lmask)] = tval;
    if (selpos) s_tp[offP + __popc(bp & lmask)] = tval;
    __syncthreads();

    // ---- pairwise: thread owns batch element tid ----
    float acc = 0.f;
    #pragma unroll 4
    for (int k = 0; k < totN; k++) {
        float d = s_tn[k] - apos;        // e + g - y
        float r = fmaxf(d, 0.f);
        acc = fmaf(r, r, acc);
    }
    #pragma unroll 4
    for (int k = 0; k < totP; k++) {
        float d = s_tp[k] - aneg;        // y - e + g
        float r = fmaxf(d, 0.f);
        acc = fmaf(r, r, acc);
    }

    // ---- reduce: warp shuffle, then warp 0 over 8 partials ----
    #pragma unroll
    for (int o = 16; o > 0; o >>= 1)
        acc += __shfl_down_sync(0xffffffffu, acc, o);
    __shared__ float wsum[8];
    if (lane == 0) wsum[w] = acc;
    __syncthreads();
    if (w == 0) {
        float v = (lane < 8) ? wsum[lane] : 0.f;
        #pragma unroll
        for (int o = 4; o > 0; o >>= 1)
            v += __shfl_down_sync(0xffffffffu, v, o);
        if (lane == 0) d_part[c * MAXCH + blockIdx.x] = v;
    }
}

__global__ void __launch_bounds__(TPB)
finalize_kernel(float* __restrict__ out, int Bn, int Cn, int chunks)
{
    int tid  = threadIdx.x;
    int lane = tid & 31, w = tid >> 5;

    // warp w handles classes w, w+8, ... — everything here is L2-hot
    __shared__ float sres[MAXC];
    for (int cc = w; cc < Cn; cc += 8) {
        float m = 0.f;
        for (int k = lane; k < chunks; k += 32)
            m += d_part[cc * MAXCH + k];
        #pragma unroll
        for (int o = 16; o > 0; o >>= 1)
            m += __shfl_down_sync(0xffffffffu, m, o);
        if (lane == 0) {
            float res = m / 1000.0f;            // m2/MAX_POS + m3/MAX_NEG
            if (isnan(res)) res = 0.f;
            int np = d_npos[cc];
            if (np == 0 || np == Bn) res = d_sumyp[cc] * 1e-8f;
            sres[cc] = res;
        }
    }
    __syncthreads();
    if (w == 0) {
        float r = (lane < Cn) ? sres[lane] : 0.f;
        #pragma unroll
        for (int o = 16; o > 0; o >>= 1)
            r += __shfl_down_sync(0xffffffffu, r, o);
        if (lane == 0) out[0] = r / (float)Cn;
    }
}

extern "C" void kernel_launch(void* const* d_in, const int* in_sizes, int n_in,
                              void* d_out, int out_size)
{
    const float* y_pred     = (const float*)d_in[0];
    const float* y_true     = (const float*)d_in[1];
    const float* epoch_pred = (const float*)d_in[2];
    const float* epoch_true = (const float*)d_in[3];
    const float* gamma      = (const float*)d_in[4];
    const float* rand_pos   = (const float*)d_in[5];
    const float* rand_neg   = (const float*)d_in[6];

    int Cn = in_sizes[4];            // gamma: [C]
    int Bn = in_sizes[0] / Cn;       // y_pred: [B, C]
    int En = in_sizes[2] / Cn;       // epoch_pred: [E, C]
    int chunks = (En + TPB - 1) / TPB;

    count_kernel<<<Cn, TPB>>>(epoch_true, y_pred, y_true, Bn, Cn, En);
    dim3 grid(chunks, Cn);
    loss_kernel<<<grid, TPB>>>(epoch_pred, epoch_true, rand_pos, rand_neg,
                               gamma, y_pred, y_true, Bn, Cn, En);
    finalize_kernel<<<1, TPB>>>((float*)d_out, Bn, Cn, chunks);
}